// round 1
// baseline (speedup 1.0000x reference)
#include <cuda_runtime.h>
#include <cuda_bf16.h>
#include <math.h>

// ---------------------------------------------------------------------------
// Swin Transformer encoder layer, GB300 round-1 (fp32 SIMT).
// B=4, H=W=128, E=512, NH=16, HD=32, 8x8 windows, DFF=2048, post-norm.
//
// Pipeline:
//   1. QKV GEMM   (65536x1536x512)  -> window-permuted scratch  g_qkv
//   2. Attention  per (window, head) with fused rel-pos bias + softmax
//   3. OutProj GEMM (65536x512x512) -> token-permuted scratch   g_t0
//   4. add + LN1  -> g_z
//   5. FFN1 GEMM  (65536x2048x512) + ReLU -> g_h
//   6. FFN2 GEMM  (65536x512x2048) -> g_t0
//   7. add + LN2  -> d_out
// ---------------------------------------------------------------------------

#define T_TOK   65536     // B*H*W
#define E_DIM   512
#define QKV_N   1536
#define DFF_N   2048
#define NWIN    1024      // B * 16 * 16
#define NH_     16
#define HD_     32
#define NTOK_W  64        // tokens per window

// scratch (allocation-guard-safe: static __device__ globals)
__device__ float g_qkv[(size_t)T_TOK * QKV_N];   // window layout rows
__device__ float g_attn[(size_t)T_TOK * E_DIM];  // window layout rows
__device__ float g_t0[(size_t)T_TOK * E_DIM];    // token layout
__device__ float g_z[(size_t)T_TOK * E_DIM];     // token layout (post LN1)
__device__ float g_h[(size_t)T_TOK * DFF_N];     // token layout

// ---------------------------------------------------------------------------
// Row permutations (fused into GEMM epilogue; each row stays coalesced)
// ---------------------------------------------------------------------------
__device__ __forceinline__ int to_win_row(int m) {
    // token index -> window-layout row (win*64 + n)
    int b = m >> 14;
    int p = m & 16383;
    int r = p >> 7;
    int c = p & 127;
    int win = (b << 8) + ((r >> 3) << 4) + (c >> 3);
    int n   = ((r & 7) << 3) + (c & 7);
    return (win << 6) + n;
}
__device__ __forceinline__ int from_win_row(int m) {
    // window-layout row -> token index
    int win = m >> 6, n = m & 63;
    int b  = win >> 8, wi = win & 255;
    int wr = wi >> 4,  wc = wi & 15;
    int r = (wr << 3) + (n >> 3);
    int c = (wc << 3) + (n & 7);
    return (b << 14) + (r << 7) + c;
}

// ---------------------------------------------------------------------------
// Generic NT SGEMM: C[m][n] = sum_k A[m][k] * B[n][k] + bias[n]
// A: MxK row-major, B: NxK row-major. 128x128 block tile, 16 K-tile,
// 8x8 per thread, 256 threads.
// EPI: 0 = bias, 1 = bias+relu.  PERM: 0 = none, 1 = to_win, 2 = from_win.
// ---------------------------------------------------------------------------
#define BM 128
#define BN 128
#define BK 16
#define TM 8
#define TN 8

template <int EPI, int PERM>
__global__ void __launch_bounds__(256, 2) gemm_nt(
    const float* __restrict__ A, const float* __restrict__ B,
    const float* __restrict__ bias, float* __restrict__ C,
    int M, int N, int K)
{
    __shared__ float As[BK][BM + 4];
    __shared__ float Bs[BK][BN + 4];

    const int tid = threadIdx.x;
    const int bm = blockIdx.y * BM;
    const int bn = blockIdx.x * BN;

    // load indices: 2 x float4 per thread per matrix tile
    const int lr = tid >> 2;          // 0..63
    const int lc = (tid & 3) * 4;     // 0,4,8,12

    // compute indices
    const int tx = tid & 15;          // 0..15 -> cols
    const int ty = tid >> 4;          // 0..15 -> rows

    float acc[TM][TN];
#pragma unroll
    for (int i = 0; i < TM; i++)
#pragma unroll
        for (int j = 0; j < TN; j++) acc[i][j] = 0.f;

    const float* Aptr0 = A + (size_t)(bm + lr) * K + lc;
    const float* Aptr1 = A + (size_t)(bm + lr + 64) * K + lc;
    const float* Bptr0 = B + (size_t)(bn + lr) * K + lc;
    const float* Bptr1 = B + (size_t)(bn + lr + 64) * K + lc;

    for (int kt = 0; kt < K; kt += BK) {
        float4 a0 = *(const float4*)(Aptr0 + kt);
        float4 a1 = *(const float4*)(Aptr1 + kt);
        float4 b0 = *(const float4*)(Bptr0 + kt);
        float4 b1 = *(const float4*)(Bptr1 + kt);

        __syncthreads();
        As[lc + 0][lr] = a0.x; As[lc + 1][lr] = a0.y;
        As[lc + 2][lr] = a0.z; As[lc + 3][lr] = a0.w;
        As[lc + 0][lr + 64] = a1.x; As[lc + 1][lr + 64] = a1.y;
        As[lc + 2][lr + 64] = a1.z; As[lc + 3][lr + 64] = a1.w;
        Bs[lc + 0][lr] = b0.x; Bs[lc + 1][lr] = b0.y;
        Bs[lc + 2][lr] = b0.z; Bs[lc + 3][lr] = b0.w;
        Bs[lc + 0][lr + 64] = b1.x; Bs[lc + 1][lr + 64] = b1.y;
        Bs[lc + 2][lr + 64] = b1.z; Bs[lc + 3][lr + 64] = b1.w;
        __syncthreads();

#pragma unroll
        for (int k = 0; k < BK; k++) {
            float af[TM], bf[TN];
#pragma unroll
            for (int i = 0; i < TM; i++) af[i] = As[k][ty * TM + i];
#pragma unroll
            for (int j = 0; j < TN; j++) bf[j] = Bs[k][tx * TN + j];
#pragma unroll
            for (int i = 0; i < TM; i++)
#pragma unroll
                for (int j = 0; j < TN; j++)
                    acc[i][j] = fmaf(af[i], bf[j], acc[i][j]);
        }
    }

    // epilogue
    float bv[TN];
#pragma unroll
    for (int j = 0; j < TN; j++) bv[j] = bias[bn + tx * TN + j];

#pragma unroll
    for (int i = 0; i < TM; i++) {
        int row = bm + ty * TM + i;
        int orow;
        if (PERM == 0)      orow = row;
        else if (PERM == 1) orow = to_win_row(row);
        else                orow = from_win_row(row);
        float* cp = C + (size_t)orow * N + bn + tx * TN;
        float v[TN];
#pragma unroll
        for (int j = 0; j < TN; j++) {
            float t = acc[i][j] + bv[j];
            if (EPI == 1) t = fmaxf(t, 0.f);
            v[j] = t;
        }
        *(float4*)(cp)     = make_float4(v[0], v[1], v[2], v[3]);
        *(float4*)(cp + 4) = make_float4(v[4], v[5], v[6], v[7]);
    }
}

// ---------------------------------------------------------------------------
// Window attention: one block per (window, head). N=64 tokens, HD=32.
// 256 threads: thread t owns q = t/4, and 16 keys (scores) / 8 dims (AV).
// ---------------------------------------------------------------------------
__global__ void __launch_bounds__(256) attn_kernel(
    const float* __restrict__ qkv, const float* __restrict__ pos_emb,
    float* __restrict__ out)
{
    const int win = blockIdx.x;
    const int head = blockIdx.y;
    const int tid = threadIdx.x;

    __shared__ float Qs[64][33];
    __shared__ float Ks[64][33];
    __shared__ float Vs[64][33];
    __shared__ float Ps[64][65];
    __shared__ float bias_s[225];

    // cooperative load of Q/K/V tiles (64x32 each)
    {
        int n  = tid >> 2;
        int c0 = (tid & 3) * 8;
        size_t base = ((size_t)win * 64 + n) * (size_t)QKV_N + head * HD_ + c0;
        float4 a = *(const float4*)(qkv + base);
        float4 b = *(const float4*)(qkv + base + 4);
        Qs[n][c0 + 0] = a.x; Qs[n][c0 + 1] = a.y; Qs[n][c0 + 2] = a.z; Qs[n][c0 + 3] = a.w;
        Qs[n][c0 + 4] = b.x; Qs[n][c0 + 5] = b.y; Qs[n][c0 + 6] = b.z; Qs[n][c0 + 7] = b.w;
        a = *(const float4*)(qkv + base + 512);
        b = *(const float4*)(qkv + base + 516);
        Ks[n][c0 + 0] = a.x; Ks[n][c0 + 1] = a.y; Ks[n][c0 + 2] = a.z; Ks[n][c0 + 3] = a.w;
        Ks[n][c0 + 4] = b.x; Ks[n][c0 + 5] = b.y; Ks[n][c0 + 6] = b.z; Ks[n][c0 + 7] = b.w;
        a = *(const float4*)(qkv + base + 1024);
        b = *(const float4*)(qkv + base + 1028);
        Vs[n][c0 + 0] = a.x; Vs[n][c0 + 1] = a.y; Vs[n][c0 + 2] = a.z; Vs[n][c0 + 3] = a.w;
        Vs[n][c0 + 4] = b.x; Vs[n][c0 + 5] = b.y; Vs[n][c0 + 6] = b.z; Vs[n][c0 + 7] = b.w;
    }
    if (tid < 225) bias_s[tid] = pos_emb[tid];
    __syncthreads();

    const int q = tid >> 2;
    const int sub = tid & 3;
    const int qh = q >> 3, qw = q & 7;

    // scores for 16 keys
    float s[16];
    float mx = -1e30f;
#pragma unroll
    for (int kk = 0; kk < 16; kk++) {
        int k = sub * 16 + kk;
        float acc = 0.f;
#pragma unroll
        for (int d = 0; d < 32; d++) acc = fmaf(Qs[q][d], Ks[k][d], acc);
        int kh = k >> 3, kw = k & 7;
        acc = acc * 0.17677669529663687f + bias_s[(kh - qh + 7) * 15 + (kw - qw + 7)];
        s[kk] = acc;
        mx = fmaxf(mx, acc);
    }
    // reduce over the 4 lanes that share q (consecutive lanes)
    mx = fmaxf(mx, __shfl_xor_sync(0xffffffffu, mx, 1));
    mx = fmaxf(mx, __shfl_xor_sync(0xffffffffu, mx, 2));
    float sum = 0.f;
#pragma unroll
    for (int kk = 0; kk < 16; kk++) {
        float p = __expf(s[kk] - mx);
        s[kk] = p;
        sum += p;
    }
    sum += __shfl_xor_sync(0xffffffffu, sum, 1);
    sum += __shfl_xor_sync(0xffffffffu, sum, 2);
    float inv = 1.f / sum;
#pragma unroll
    for (int kk = 0; kk < 16; kk++) Ps[q][sub * 16 + kk] = s[kk] * inv;
    __syncthreads();

    // O = P @ V : thread owns (q, 8 dims)
    const int d0 = sub * 8;
    float o[8];
#pragma unroll
    for (int j = 0; j < 8; j++) o[j] = 0.f;
#pragma unroll
    for (int k = 0; k < 64; k++) {
        float p = Ps[q][k];
#pragma unroll
        for (int j = 0; j < 8; j++) o[j] = fmaf(p, Vs[k][d0 + j], o[j]);
    }
    size_t ob = ((size_t)win * 64 + q) * (size_t)E_DIM + head * HD_ + d0;
    *(float4*)(out + ob)     = make_float4(o[0], o[1], o[2], o[3]);
    *(float4*)(out + ob + 4) = make_float4(o[4], o[5], o[6], o[7]);
}

// ---------------------------------------------------------------------------
// out[row] = LayerNorm(a[row] + b[row]) * g + be    (E=512, 128 threads/row)
// ---------------------------------------------------------------------------
__global__ void __launch_bounds__(128) add_ln_kernel(
    const float* __restrict__ A, const float* __restrict__ Bv,
    const float* __restrict__ g, const float* __restrict__ be,
    float* __restrict__ out)
{
    const int row = blockIdx.x;
    const int tid = threadIdx.x;
    size_t base = (size_t)row * E_DIM + tid * 4;

    float4 a = *(const float4*)(A + base);
    float4 b = *(const float4*)(Bv + base);
    float y0 = a.x + b.x, y1 = a.y + b.y, y2 = a.z + b.z, y3 = a.w + b.w;

    float s  = y0 + y1 + y2 + y3;
    float s2 = y0 * y0 + y1 * y1 + y2 * y2 + y3 * y3;
#pragma unroll
    for (int off = 16; off; off >>= 1) {
        s  += __shfl_down_sync(0xffffffffu, s, off);
        s2 += __shfl_down_sync(0xffffffffu, s2, off);
    }
    __shared__ float ss[4], ss2[4];
    int warp = tid >> 5, lane = tid & 31;
    if (lane == 0) { ss[warp] = s; ss2[warp] = s2; }
    __syncthreads();
    s  = ss[0] + ss[1] + ss[2] + ss[3];
    s2 = ss2[0] + ss2[1] + ss2[2] + ss2[3];

    const float rE = 1.f / 512.f;
    float mean = s * rE;
    float var  = s2 * rE - mean * mean;
    float rstd = rsqrtf(var + 1e-5f);

    int e = tid * 4;
    float4 gw = *(const float4*)(g + e);
    float4 bb = *(const float4*)(be + e);
    float4 o;
    o.x = (y0 - mean) * rstd * gw.x + bb.x;
    o.y = (y1 - mean) * rstd * gw.y + bb.y;
    o.z = (y2 - mean) * rstd * gw.z + bb.z;
    o.w = (y3 - mean) * rstd * gw.w + bb.w;
    *(float4*)(out + base) = o;
}

// ---------------------------------------------------------------------------
// launch
// ---------------------------------------------------------------------------
extern "C" void kernel_launch(void* const* d_in, const int* in_sizes, int n_in,
                              void* d_out, int out_size)
{
    const float* x     = (const float*)d_in[0];
    const float* w_qkv = (const float*)d_in[1];
    const float* b_qkv = (const float*)d_in[2];
    const float* w_out = (const float*)d_in[3];
    const float* b_out = (const float*)d_in[4];
    const float* pos   = (const float*)d_in[5];
    const float* w1    = (const float*)d_in[6];
    const float* b1    = (const float*)d_in[7];
    const float* w2    = (const float*)d_in[8];
    const float* b2    = (const float*)d_in[9];
    const float* ln1w  = (const float*)d_in[10];
    const float* ln1b  = (const float*)d_in[11];
    const float* ln2w  = (const float*)d_in[12];
    const float* ln2b  = (const float*)d_in[13];
    float* out = (float*)d_out;

    static float *p_qkv = nullptr, *p_attn = nullptr, *p_t0 = nullptr,
                 *p_z = nullptr, *p_h = nullptr;
    if (!p_qkv) {
        cudaGetSymbolAddress((void**)&p_qkv,  g_qkv);
        cudaGetSymbolAddress((void**)&p_attn, g_attn);
        cudaGetSymbolAddress((void**)&p_t0,   g_t0);
        cudaGetSymbolAddress((void**)&p_z,    g_z);
        cudaGetSymbolAddress((void**)&p_h,    g_h);
    }

    // 1. QKV projection (rows scattered into window layout)
    gemm_nt<0, 1><<<dim3(QKV_N / BN, T_TOK / BM), 256>>>(
        x, w_qkv, b_qkv, p_qkv, T_TOK, QKV_N, E_DIM);

    // 2. window attention
    attn_kernel<<<dim3(NWIN, NH_), 256>>>(p_qkv, pos, p_attn);

    // 3. output projection (rows scattered back to token layout)
    gemm_nt<0, 2><<<dim3(E_DIM / BN, T_TOK / BM), 256>>>(
        p_attn, w_out, b_out, p_t0, T_TOK, E_DIM, E_DIM);

    // 4. residual + LN1
    add_ln_kernel<<<T_TOK, 128>>>(x, p_t0, ln1w, ln1b, p_z);

    // 5. FFN up + ReLU
    gemm_nt<1, 0><<<dim3(DFF_N / BN, T_TOK / BM), 256>>>(
        p_z, w1, b1, p_h, T_TOK, DFF_N, E_DIM);

    // 6. FFN down
    gemm_nt<0, 0><<<dim3(E_DIM / BN, T_TOK / BM), 256>>>(
        p_h, w2, b2, p_t0, T_TOK, E_DIM, DFF_N);

    // 7. residual + LN2 -> final output
    add_ln_kernel<<<T_TOK, 128>>>(p_z, p_t0, ln2w, ln2b, out);
}

// round 3
// speedup vs baseline: 2.2654x; 2.2654x over previous
#include <cuda_runtime.h>
#include <cuda_bf16.h>
#include <cstdint>
#include <math.h>

// ---------------------------------------------------------------------------
// Swin Transformer encoder layer, GB300 round-3: TF32 tensor-core GEMMs.
// (round-2 kernel + missing <cstdint> include)
// ---------------------------------------------------------------------------

#define T_TOK   65536
#define E_DIM   512
#define QKV_N   1536
#define DFF_N   2048
#define NWIN    1024
#define NH_     16
#define HD_     32

__device__ float g_qkv[(size_t)T_TOK * QKV_N];
__device__ float g_attn[(size_t)T_TOK * E_DIM];
__device__ float g_t0[(size_t)T_TOK * E_DIM];
__device__ float g_z[(size_t)T_TOK * E_DIM];
__device__ float g_h[(size_t)T_TOK * DFF_N];

__device__ __forceinline__ int to_win_row(int m) {
    int b = m >> 14, p = m & 16383;
    int r = p >> 7, c = p & 127;
    int win = (b << 8) + ((r >> 3) << 4) + (c >> 3);
    int n   = ((r & 7) << 3) + (c & 7);
    return (win << 6) + n;
}
__device__ __forceinline__ int from_win_row(int m) {
    int win = m >> 6, n = m & 63;
    int b  = win >> 8, wi = win & 255;
    int wr = wi >> 4,  wc = wi & 15;
    int r = (wr << 3) + (n >> 3);
    int c = (wc << 3) + (n & 7);
    return (b << 14) + (r << 7) + c;
}

__device__ __forceinline__ uint32_t f2tf32(float x) {
    uint32_t r;
    asm("cvt.rna.tf32.f32 %0, %1;" : "=r"(r) : "f"(x));
    return r;
}

__device__ __forceinline__ void mma_tf32(float c[4], const uint32_t a[4], const uint32_t b[2]) {
    asm volatile(
        "mma.sync.aligned.m16n8k8.row.col.f32.tf32.tf32.f32 "
        "{%0,%1,%2,%3},{%4,%5,%6,%7},{%8,%9},{%0,%1,%2,%3};\n"
        : "+f"(c[0]), "+f"(c[1]), "+f"(c[2]), "+f"(c[3])
        : "r"(a[0]), "r"(a[1]), "r"(a[2]), "r"(a[3]), "r"(b[0]), "r"(b[1]));
}

// ---------------------------------------------------------------------------
// TF32 NT GEMM: C[m][n] = sum_k A[m][k]*B[n][k] + bias[n].
// Block 128x128, BK=16, 128 threads (4 warps, 2x2), warp tile 64x64.
// Smem holds tiles pre-packed in mma fragment order:
//   A value (r in 16-tile, c in 8-kstep) -> lane=(r%8)*4+(c%4), reg=(r/8)+2*(c/4)
//   B value (k, n in 8-tile)             -> lane=(n%8)*4+(k%4), reg=k/4
// EPI: 0 bias, 1 bias+relu.  PERM: 0 none, 1 to_win, 2 from_win.
// ---------------------------------------------------------------------------
template <int EPI, int PERM>
__global__ void __launch_bounds__(128, 2) gemm_tf32(
    const float* __restrict__ A, const float* __restrict__ B,
    const float* __restrict__ bias, float* __restrict__ C,
    int M, int N, int K)
{
    __shared__ uint32_t As[2048];   // [s][mtile(8)][lane][4]
    __shared__ uint32_t Bs[2048];   // [s][ntile(16)][lane][2]

    const int tid  = threadIdx.x;
    const int lane = tid & 31;
    const int warp = tid >> 5;
    const int wr = warp >> 1, wc = warp & 1;
    const int bm = blockIdx.y << 7;
    const int bn = blockIdx.x << 7;

    const int c4   = tid & 3;
    const int s0   = c4 >> 1;
    const int regA = ((tid >> 5) & 1) + ((c4 & 1) << 1);
    const int regB = c4 & 1;
    const int lb   = ((tid >> 2) & 7) << 2;

    int awb[4], bwb[4];
    const float *ap[4], *bp[4];
#pragma unroll
    for (int q = 0; q < 4; q++) {
        awb[q] = ((s0 * 8 + (tid >> 6) + 2 * q) * 32 + lb) * 4 + regA;
        bwb[q] = ((s0 * 16 + (tid >> 5) + 4 * q) * 32 + lb) * 2 + regB;
        int row = (tid >> 2) + 32 * q;
        ap[q] = A + (size_t)(bm + row) * K + (c4 << 2);
        bp[q] = B + (size_t)(bn + row) * K + (c4 << 2);
    }

    float acc[4][8][4];
#pragma unroll
    for (int i = 0; i < 4; i++)
#pragma unroll
        for (int j = 0; j < 8; j++)
#pragma unroll
            for (int v = 0; v < 4; v++) acc[i][j][v] = 0.f;

    float4 fa[4], fb[4];
#pragma unroll
    for (int q = 0; q < 4; q++) {
        fa[q] = *(const float4*)ap[q];  ap[q] += 16;
        fb[q] = *(const float4*)bp[q];  bp[q] += 16;
    }

    const int ntiles = K >> 4;
    for (int t = 0; t < ntiles; t++) {
        __syncthreads();
#pragma unroll
        for (int q = 0; q < 4; q++) {
            As[awb[q] + 0]  = f2tf32(fa[q].x);
            As[awb[q] + 4]  = f2tf32(fa[q].y);
            As[awb[q] + 8]  = f2tf32(fa[q].z);
            As[awb[q] + 12] = f2tf32(fa[q].w);
            Bs[bwb[q] + 0]  = f2tf32(fb[q].x);
            Bs[bwb[q] + 2]  = f2tf32(fb[q].y);
            Bs[bwb[q] + 4]  = f2tf32(fb[q].z);
            Bs[bwb[q] + 6]  = f2tf32(fb[q].w);
        }
        __syncthreads();

        if (t + 1 < ntiles) {
#pragma unroll
            for (int q = 0; q < 4; q++) {
                fa[q] = *(const float4*)ap[q];  ap[q] += 16;
                fb[q] = *(const float4*)bp[q];  bp[q] += 16;
            }
        }

#pragma unroll
        for (int s = 0; s < 2; s++) {
            uint4 afr[4];
            uint2 bfr[8];
#pragma unroll
            for (int i = 0; i < 4; i++)
                afr[i] = *(const uint4*)&As[((s * 8 + wr * 4 + i) * 32 + lane) * 4];
#pragma unroll
            for (int j = 0; j < 8; j++)
                bfr[j] = *(const uint2*)&Bs[((s * 16 + wc * 8 + j) * 32 + lane) * 2];
#pragma unroll
            for (int i = 0; i < 4; i++)
#pragma unroll
                for (int j = 0; j < 8; j++)
                    mma_tf32(acc[i][j], (const uint32_t*)&afr[i], (const uint32_t*)&bfr[j]);
        }
    }

    // epilogue
    const int r  = lane >> 2;
    const int cc = (lane & 3) << 1;
#pragma unroll
    for (int i = 0; i < 4; i++) {
        int row0 = bm + wr * 64 + i * 16 + r;
        int row1 = row0 + 8;
        int o0, o1;
        if (PERM == 0)      { o0 = row0;              o1 = row1; }
        else if (PERM == 1) { o0 = to_win_row(row0);  o1 = to_win_row(row1); }
        else                { o0 = from_win_row(row0); o1 = from_win_row(row1); }
#pragma unroll
        for (int j = 0; j < 8; j++) {
            int gn = bn + wc * 64 + j * 8 + cc;
            float b0 = bias[gn], b1 = bias[gn + 1];
            float v00 = acc[i][j][0] + b0, v01 = acc[i][j][1] + b1;
            float v10 = acc[i][j][2] + b0, v11 = acc[i][j][3] + b1;
            if (EPI == 1) {
                v00 = fmaxf(v00, 0.f); v01 = fmaxf(v01, 0.f);
                v10 = fmaxf(v10, 0.f); v11 = fmaxf(v11, 0.f);
            }
            *(float2*)&C[(size_t)o0 * N + gn] = make_float2(v00, v01);
            *(float2*)&C[(size_t)o1 * N + gn] = make_float2(v10, v11);
        }
    }
}

// ---------------------------------------------------------------------------
// Window attention: one block per (window, head). 4x4 register micro-tiles.
// ---------------------------------------------------------------------------
__global__ void __launch_bounds__(256) attn_kernel(
    const float* __restrict__ qkv, const float* __restrict__ pos_emb,
    float* __restrict__ out)
{
    const int win = blockIdx.x;
    const int head = blockIdx.y;
    const int tid = threadIdx.x;

    __shared__ float Qt[32 * 68];   // [d][q]
    __shared__ float Kt[32 * 68];   // [d][k]
    __shared__ float Vs[64 * 36];   // [k][d]
    __shared__ float Pt[64 * 68];   // [k][q]
    __shared__ float bias_s[225];

    {
        int n  = tid >> 2;
        int c0 = (tid & 3) << 3;
        size_t base = ((size_t)win * 64 + n) * (size_t)QKV_N + head * HD_ + c0;
        float4 a = *(const float4*)(qkv + base);
        float4 b = *(const float4*)(qkv + base + 4);
        Qt[(c0 + 0) * 68 + n] = a.x; Qt[(c0 + 1) * 68 + n] = a.y;
        Qt[(c0 + 2) * 68 + n] = a.z; Qt[(c0 + 3) * 68 + n] = a.w;
        Qt[(c0 + 4) * 68 + n] = b.x; Qt[(c0 + 5) * 68 + n] = b.y;
        Qt[(c0 + 6) * 68 + n] = b.z; Qt[(c0 + 7) * 68 + n] = b.w;
        a = *(const float4*)(qkv + base + 512);
        b = *(const float4*)(qkv + base + 516);
        Kt[(c0 + 0) * 68 + n] = a.x; Kt[(c0 + 1) * 68 + n] = a.y;
        Kt[(c0 + 2) * 68 + n] = a.z; Kt[(c0 + 3) * 68 + n] = a.w;
        Kt[(c0 + 4) * 68 + n] = b.x; Kt[(c0 + 5) * 68 + n] = b.y;
        Kt[(c0 + 6) * 68 + n] = b.z; Kt[(c0 + 7) * 68 + n] = b.w;
        a = *(const float4*)(qkv + base + 1024);
        b = *(const float4*)(qkv + base + 1028);
        *(float4*)&Vs[n * 36 + c0]     = a;
        *(float4*)&Vs[n * 36 + c0 + 4] = b;
    }
    if (tid < 225) bias_s[tid] = pos_emb[tid];
    __syncthreads();

    const int tq = tid >> 4;
    const int tk = tid & 15;

    float s[4][4];
#pragma unroll
    for (int a = 0; a < 4; a++)
#pragma unroll
        for (int b = 0; b < 4; b++) s[a][b] = 0.f;

#pragma unroll 8
    for (int d = 0; d < 32; d++) {
        float4 qf = *(const float4*)&Qt[d * 68 + tq * 4];
        float4 kf = *(const float4*)&Kt[d * 68 + tk * 4];
        const float* qa = (const float*)&qf;
        const float* ka = (const float*)&kf;
#pragma unroll
        for (int a = 0; a < 4; a++)
#pragma unroll
            for (int b = 0; b < 4; b++)
                s[a][b] = fmaf(qa[a], ka[b], s[a][b]);
    }

    const float scl = 0.17677669529663687f;
#pragma unroll
    for (int a = 0; a < 4; a++) {
        int q = tq * 4 + a, qh = q >> 3, qw = q & 7;
#pragma unroll
        for (int b = 0; b < 4; b++) {
            int k = tk * 4 + b, kh = k >> 3, kw = k & 7;
            s[a][b] = s[a][b] * scl + bias_s[(kh - qh + 7) * 15 + (kw - qw + 7)];
        }
    }

    float mx[4], sm[4];
#pragma unroll
    for (int a = 0; a < 4; a++)
        mx[a] = fmaxf(fmaxf(s[a][0], s[a][1]), fmaxf(s[a][2], s[a][3]));
#pragma unroll
    for (int off = 8; off; off >>= 1)
#pragma unroll
        for (int a = 0; a < 4; a++)
            mx[a] = fmaxf(mx[a], __shfl_xor_sync(0xffffffffu, mx[a], off));
#pragma unroll
    for (int a = 0; a < 4; a++) {
        sm[a] = 0.f;
#pragma unroll
        for (int b = 0; b < 4; b++) {
            s[a][b] = __expf(s[a][b] - mx[a]);
            sm[a] += s[a][b];
        }
    }
#pragma unroll
    for (int off = 8; off; off >>= 1)
#pragma unroll
        for (int a = 0; a < 4; a++)
            sm[a] += __shfl_xor_sync(0xffffffffu, sm[a], off);
    float inv[4];
#pragma unroll
    for (int a = 0; a < 4; a++) inv[a] = 1.f / sm[a];

#pragma unroll
    for (int b = 0; b < 4; b++) {
        float4 v = make_float4(s[0][b] * inv[0], s[1][b] * inv[1],
                               s[2][b] * inv[2], s[3][b] * inv[3]);
        *(float4*)&Pt[(tk * 4 + b) * 68 + tq * 4] = v;
    }
    __syncthreads();

    // O = P @ V
    const int td = tid & 15;
    float o[4][2];
#pragma unroll
    for (int a = 0; a < 4; a++) { o[a][0] = 0.f; o[a][1] = 0.f; }
#pragma unroll 8
    for (int k = 0; k < 64; k++) {
        float4 pf = *(const float4*)&Pt[k * 68 + tq * 4];
        float2 vf = *(const float2*)&Vs[k * 36 + td * 2];
        const float* pa = (const float*)&pf;
#pragma unroll
        for (int a = 0; a < 4; a++) {
            o[a][0] = fmaf(pa[a], vf.x, o[a][0]);
            o[a][1] = fmaf(pa[a], vf.y, o[a][1]);
        }
    }
#pragma unroll
    for (int a = 0; a < 4; a++) {
        int q = tq * 4 + a;
        size_t ob = ((size_t)win * 64 + q) * (size_t)E_DIM + head * HD_ + td * 2;
        *(float2*)&out[ob] = make_float2(o[a][0], o[a][1]);
    }
}

// ---------------------------------------------------------------------------
// out[row] = LayerNorm(a[row] + b[row]) * g + be
// ---------------------------------------------------------------------------
__global__ void __launch_bounds__(128) add_ln_kernel(
    const float* __restrict__ A, const float* __restrict__ Bv,
    const float* __restrict__ g, const float* __restrict__ be,
    float* __restrict__ out)
{
    const int row = blockIdx.x;
    const int tid = threadIdx.x;
    size_t base = (size_t)row * E_DIM + tid * 4;

    float4 a = *(const float4*)(A + base);
    float4 b = *(const float4*)(Bv + base);
    float y0 = a.x + b.x, y1 = a.y + b.y, y2 = a.z + b.z, y3 = a.w + b.w;

    float s  = y0 + y1 + y2 + y3;
    float s2 = y0 * y0 + y1 * y1 + y2 * y2 + y3 * y3;
#pragma unroll
    for (int off = 16; off; off >>= 1) {
        s  += __shfl_down_sync(0xffffffffu, s, off);
        s2 += __shfl_down_sync(0xffffffffu, s2, off);
    }
    __shared__ float ss[4], ss2[4];
    int warp = tid >> 5, lane = tid & 31;
    if (lane == 0) { ss[warp] = s; ss2[warp] = s2; }
    __syncthreads();
    s  = ss[0] + ss[1] + ss[2] + ss[3];
    s2 = ss2[0] + ss2[1] + ss2[2] + ss2[3];

    const float rE = 1.f / 512.f;
    float mean = s * rE;
    float var  = s2 * rE - mean * mean;
    float rstd = rsqrtf(var + 1e-5f);

    int e = tid * 4;
    float4 gw = *(const float4*)(g + e);
    float4 bb = *(const float4*)(be + e);
    float4 o;
    o.x = (y0 - mean) * rstd * gw.x + bb.x;
    o.y = (y1 - mean) * rstd * gw.y + bb.y;
    o.z = (y2 - mean) * rstd * gw.z + bb.z;
    o.w = (y3 - mean) * rstd * gw.w + bb.w;
    *(float4*)(out + base) = o;
}

// ---------------------------------------------------------------------------
extern "C" void kernel_launch(void* const* d_in, const int* in_sizes, int n_in,
                              void* d_out, int out_size)
{
    const float* x     = (const float*)d_in[0];
    const float* w_qkv = (const float*)d_in[1];
    const float* b_qkv = (const float*)d_in[2];
    const float* w_out = (const float*)d_in[3];
    const float* b_out = (const float*)d_in[4];
    const float* pos   = (const float*)d_in[5];
    const float* w1    = (const float*)d_in[6];
    const float* b1    = (const float*)d_in[7];
    const float* w2    = (const float*)d_in[8];
    const float* b2    = (const float*)d_in[9];
    const float* ln1w  = (const float*)d_in[10];
    const float* ln1b  = (const float*)d_in[11];
    const float* ln2w  = (const float*)d_in[12];
    const float* ln2b  = (const float*)d_in[13];
    float* out = (float*)d_out;

    static float *p_qkv = nullptr, *p_attn = nullptr, *p_t0 = nullptr,
                 *p_z = nullptr, *p_h = nullptr;
    if (!p_qkv) {
        cudaGetSymbolAddress((void**)&p_qkv,  g_qkv);
        cudaGetSymbolAddress((void**)&p_attn, g_attn);
        cudaGetSymbolAddress((void**)&p_t0,   g_t0);
        cudaGetSymbolAddress((void**)&p_z,    g_z);
        cudaGetSymbolAddress((void**)&p_h,    g_h);
    }

    // 1. QKV projection -> window layout
    gemm_tf32<0, 1><<<dim3(QKV_N / 128, T_TOK / 128), 128>>>(
        x, w_qkv, b_qkv, p_qkv, T_TOK, QKV_N, E_DIM);

    // 2. window attention
    attn_kernel<<<dim3(NWIN, NH_), 256>>>(p_qkv, pos, p_attn);

    // 3. output projection -> token layout
    gemm_tf32<0, 2><<<dim3(E_DIM / 128, T_TOK / 128), 128>>>(
        p_attn, w_out, b_out, p_t0, T_TOK, E_DIM, E_DIM);

    // 4. residual + LN1
    add_ln_kernel<<<T_TOK, 128>>>(x, p_t0, ln1w, ln1b, p_z);

    // 5. FFN up + ReLU
    gemm_tf32<1, 0><<<dim3(DFF_N / 128, T_TOK / 128), 128>>>(
        p_z, w1, b1, p_h, T_TOK, DFF_N, E_DIM);

    // 6. FFN down
    gemm_tf32<0, 0><<<dim3(E_DIM / 128, T_TOK / 128), 128>>>(
        p_h, w2, b2, p_t0, T_TOK, E_DIM, DFF_N);

    // 7. residual + LN2 -> output
    add_ln_kernel<<<T_TOK, 128>>>(p_z, p_t0, ln2w, ln2b, out);
}

// round 4
// speedup vs baseline: 3.2192x; 1.4211x over previous
#include <cuda_runtime.h>
#include <cuda_bf16.h>
#include <cstdint>
#include <math.h>

// ---------------------------------------------------------------------------
// Swin Transformer encoder layer, GB300 round-4:
// TF32 mma GEMM with swizzled k-major smem + ldmatrix + double buffering.
// ---------------------------------------------------------------------------

#define T_TOK   65536
#define E_DIM   512
#define QKV_N   1536
#define DFF_N   2048
#define NWIN    1024
#define NH_     16
#define HD_     32

__device__ float g_qkv[(size_t)T_TOK * QKV_N];
__device__ float g_attn[(size_t)T_TOK * E_DIM];
__device__ float g_t0[(size_t)T_TOK * E_DIM];
__device__ float g_z[(size_t)T_TOK * E_DIM];
__device__ float g_h[(size_t)T_TOK * DFF_N];

__device__ __forceinline__ int to_win_row(int m) {
    int b = m >> 14, p = m & 16383;
    int r = p >> 7, c = p & 127;
    int win = (b << 8) + ((r >> 3) << 4) + (c >> 3);
    int n   = ((r & 7) << 3) + (c & 7);
    return (win << 6) + n;
}
__device__ __forceinline__ int from_win_row(int m) {
    int win = m >> 6, n = m & 63;
    int b  = win >> 8, wi = win & 255;
    int wr = wi >> 4,  wc = wi & 15;
    int r = (wr << 3) + (n >> 3);
    int c = (wc << 3) + (n & 7);
    return (b << 14) + (r << 7) + c;
}

__device__ __forceinline__ uint32_t f2tf32(float x) {
    uint32_t r;
    asm("cvt.rna.tf32.f32 %0, %1;" : "=r"(r) : "f"(x));
    return r;
}

__device__ __forceinline__ void mma_tf32(float c[4], const uint32_t a[4], const uint32_t b[2]) {
    asm volatile(
        "mma.sync.aligned.m16n8k8.row.col.f32.tf32.tf32.f32 "
        "{%0,%1,%2,%3},{%4,%5,%6,%7},{%8,%9},{%0,%1,%2,%3};\n"
        : "+f"(c[0]), "+f"(c[1]), "+f"(c[2]), "+f"(c[3])
        : "r"(a[0]), "r"(a[1]), "r"(a[2]), "r"(a[3]), "r"(b[0]), "r"(b[1]));
}

__device__ __forceinline__ void ldsm4(uint32_t& r0, uint32_t& r1, uint32_t& r2, uint32_t& r3,
                                      uint32_t addr) {
    asm volatile("ldmatrix.sync.aligned.m8n8.x4.shared.b16 {%0,%1,%2,%3}, [%4];"
                 : "=r"(r0), "=r"(r1), "=r"(r2), "=r"(r3) : "r"(addr));
}

// ---------------------------------------------------------------------------
// TF32 NT GEMM: C[m][n] = sum_k A[m][k]*B[n][k] + bias[n].
// Block 128x128, BK=16, 256 threads (8 warps as 2x4), warp tile 64x32.
// Smem: k-major 128x16 tiles, XOR-swizzled: within a 16-float row, the
// 4-float chunk index is chunk ^ ((row>>1)&3). STS.128 conflict-free;
// fragments read with ldmatrix.x4.b16 (tf32 words land in mma order).
// Double-buffered, one __syncthreads per k-tile.
// EPI: 0 bias, 1 bias+relu.  PERM: 0 none, 1 to_win, 2 from_win.
// ---------------------------------------------------------------------------
template <int EPI, int PERM>
__global__ void __launch_bounds__(256, 2) gemm_tf32(
    const float* __restrict__ A, const float* __restrict__ B,
    const float* __restrict__ bias, float* __restrict__ C,
    int M, int N, int K)
{
    __shared__ uint32_t As[2][2048];   // [buf][row*16 + swizzled chunk*4 + k%4]
    __shared__ uint32_t Bs[2][2048];

    const int tid  = threadIdx.x;
    const int lane = tid & 31;
    const int warp = tid >> 5;
    const int wr = warp >> 2;        // 0..1 : m half (64 rows)
    const int wc = warp & 3;         // 0..3 : n quarter (32 cols)
    const int bm = blockIdx.y << 7;
    const int bn = blockIdx.x << 7;

    // ---- loader indices: thread -> (row = tid>>2 (+64), k0 = (tid&3)*4)
    const int lrow = tid >> 2;             // 0..63
    const int lk   = (tid & 3) << 2;       // 0,4,8,12
    const int sw   = (((lk >> 2) ^ ((lrow >> 1) & 3)) << 2);
    const int aoff0 = lrow * 16 + sw;      // word offset in buffer
    const int aoff1 = aoff0 + 64 * 16;

    const float* aP0 = A + (size_t)(bm + lrow) * K + lk;
    const float* aP1 = A + (size_t)(bm + lrow + 64) * K + lk;
    const float* bP0 = B + (size_t)(bn + lrow) * K + lk;
    const float* bP1 = B + (size_t)(bn + lrow + 64) * K + lk;

    // ---- ldmatrix per-lane invariants
    const uint32_t asb = (uint32_t)__cvta_generic_to_shared(As);
    const uint32_t bsb = (uint32_t)__cvta_generic_to_shared(Bs);
    // A: lane -> (row-in-16 lm, chunk-hi lane>>4)
    const int lm   = (lane & 7) + (((lane >> 3) & 1) << 3);
    const int ahik = lane >> 4;                  // 0/1 : +k4
    const int amsw = (lm >> 1) & 3;
    // B: lane -> tile = lane>>3 : ntile-pair member (tile>>1), chunk-hi (tile&1)
    const int brow = lane & 7;
    const int bnt2 = (lane >> 4) & 1;            // tile>>1
    const int bhik = (lane >> 3) & 1;            // tile&1
    const int bmsw = (brow >> 1) & 3;

    float acc[4][4][4];
#pragma unroll
    for (int i = 0; i < 4; i++)
#pragma unroll
        for (int j = 0; j < 4; j++)
#pragma unroll
            for (int v = 0; v < 4; v++) acc[i][j][v] = 0.f;

    const int ntiles = K >> 4;

    // prologue: load tile 0, store to buf 0
    float4 fa0 = *(const float4*)aP0;  aP0 += 16;
    float4 fa1 = *(const float4*)aP1;  aP1 += 16;
    float4 fb0 = *(const float4*)bP0;  bP0 += 16;
    float4 fb1 = *(const float4*)bP1;  bP1 += 16;
    *(uint4*)&As[0][aoff0] = make_uint4(f2tf32(fa0.x), f2tf32(fa0.y), f2tf32(fa0.z), f2tf32(fa0.w));
    *(uint4*)&As[0][aoff1] = make_uint4(f2tf32(fa1.x), f2tf32(fa1.y), f2tf32(fa1.z), f2tf32(fa1.w));
    *(uint4*)&Bs[0][aoff0] = make_uint4(f2tf32(fb0.x), f2tf32(fb0.y), f2tf32(fb0.z), f2tf32(fb0.w));
    *(uint4*)&Bs[0][aoff1] = make_uint4(f2tf32(fb1.x), f2tf32(fb1.y), f2tf32(fb1.z), f2tf32(fb1.w));
    __syncthreads();

    for (int t = 0; t < ntiles; t++) {
        const int cur = t & 1;
        const bool more = (t + 1 < ntiles);
        if (more) {
            fa0 = *(const float4*)aP0;  aP0 += 16;
            fa1 = *(const float4*)aP1;  aP1 += 16;
            fb0 = *(const float4*)bP0;  bP0 += 16;
            fb1 = *(const float4*)bP1;  bP1 += 16;
        }

        const uint32_t abuf = asb + cur * 8192;
        const uint32_t bbuf = bsb + cur * 8192;
#pragma unroll
        for (int s = 0; s < 2; s++) {
            uint32_t afr[4][4];
#pragma unroll
            for (int i = 0; i < 4; i++) {
                int m = wr * 64 + i * 16 + lm;
                int chunk = (s * 2 + ahik) ^ amsw;
                uint32_t addr = abuf + (uint32_t)(m * 16 + chunk * 4) * 4u;
                ldsm4(afr[i][0], afr[i][1], afr[i][2], afr[i][3], addr);
            }
            uint32_t bfr[4][2];
#pragma unroll
            for (int jj = 0; jj < 2; jj++) {
                int ntile = wc * 4 + 2 * jj + bnt2;
                int n = ntile * 8 + brow;
                int chunk = (s * 2 + bhik) ^ bmsw;
                uint32_t addr = bbuf + (uint32_t)(n * 16 + chunk * 4) * 4u;
                ldsm4(bfr[2 * jj][0], bfr[2 * jj][1], bfr[2 * jj + 1][0], bfr[2 * jj + 1][1], addr);
            }
#pragma unroll
            for (int i = 0; i < 4; i++)
#pragma unroll
                for (int j = 0; j < 4; j++)
                    mma_tf32(acc[i][j], afr[i], bfr[j]);
        }

        if (more) {
            const int nxt = cur ^ 1;
            *(uint4*)&As[nxt][aoff0] = make_uint4(f2tf32(fa0.x), f2tf32(fa0.y), f2tf32(fa0.z), f2tf32(fa0.w));
            *(uint4*)&As[nxt][aoff1] = make_uint4(f2tf32(fa1.x), f2tf32(fa1.y), f2tf32(fa1.z), f2tf32(fa1.w));
            *(uint4*)&Bs[nxt][aoff0] = make_uint4(f2tf32(fb0.x), f2tf32(fb0.y), f2tf32(fb0.z), f2tf32(fb0.w));
            *(uint4*)&Bs[nxt][aoff1] = make_uint4(f2tf32(fb1.x), f2tf32(fb1.y), f2tf32(fb1.z), f2tf32(fb1.w));
            __syncthreads();
        }
    }

    // epilogue
    const int r  = lane >> 2;
    const int cc = (lane & 3) << 1;
#pragma unroll
    for (int i = 0; i < 4; i++) {
        int row0 = bm + wr * 64 + i * 16 + r;
        int row1 = row0 + 8;
        int o0, o1;
        if (PERM == 0)      { o0 = row0;               o1 = row1; }
        else if (PERM == 1) { o0 = to_win_row(row0);   o1 = to_win_row(row1); }
        else                { o0 = from_win_row(row0); o1 = from_win_row(row1); }
#pragma unroll
        for (int j = 0; j < 4; j++) {
            int gn = bn + wc * 32 + j * 8 + cc;
            float b0 = bias[gn], b1 = bias[gn + 1];
            float v00 = acc[i][j][0] + b0, v01 = acc[i][j][1] + b1;
            float v10 = acc[i][j][2] + b0, v11 = acc[i][j][3] + b1;
            if (EPI == 1) {
                v00 = fmaxf(v00, 0.f); v01 = fmaxf(v01, 0.f);
                v10 = fmaxf(v10, 0.f); v11 = fmaxf(v11, 0.f);
            }
            *(float2*)&C[(size_t)o0 * N + gn] = make_float2(v00, v01);
            *(float2*)&C[(size_t)o1 * N + gn] = make_float2(v10, v11);
        }
    }
}

// ---------------------------------------------------------------------------
// Window attention: one block per (window, head). 4x4 register micro-tiles.
// ---------------------------------------------------------------------------
__global__ void __launch_bounds__(256) attn_kernel(
    const float* __restrict__ qkv, const float* __restrict__ pos_emb,
    float* __restrict__ out)
{
    const int win = blockIdx.x;
    const int head = blockIdx.y;
    const int tid = threadIdx.x;

    __shared__ float Qt[32 * 68];
    __shared__ float Kt[32 * 68];
    __shared__ float Vs[64 * 36];
    __shared__ float Pt[64 * 68];
    __shared__ float bias_s[225];

    {
        int n  = tid >> 2;
        int c0 = (tid & 3) << 3;
        size_t base = ((size_t)win * 64 + n) * (size_t)QKV_N + head * HD_ + c0;
        float4 a = *(const float4*)(qkv + base);
        float4 b = *(const float4*)(qkv + base + 4);
        Qt[(c0 + 0) * 68 + n] = a.x; Qt[(c0 + 1) * 68 + n] = a.y;
        Qt[(c0 + 2) * 68 + n] = a.z; Qt[(c0 + 3) * 68 + n] = a.w;
        Qt[(c0 + 4) * 68 + n] = b.x; Qt[(c0 + 5) * 68 + n] = b.y;
        Qt[(c0 + 6) * 68 + n] = b.z; Qt[(c0 + 7) * 68 + n] = b.w;
        a = *(const float4*)(qkv + base + 512);
        b = *(const float4*)(qkv + base + 516);
        Kt[(c0 + 0) * 68 + n] = a.x; Kt[(c0 + 1) * 68 + n] = a.y;
        Kt[(c0 + 2) * 68 + n] = a.z; Kt[(c0 + 3) * 68 + n] = a.w;
        Kt[(c0 + 4) * 68 + n] = b.x; Kt[(c0 + 5) * 68 + n] = b.y;
        Kt[(c0 + 6) * 68 + n] = b.z; Kt[(c0 + 7) * 68 + n] = b.w;
        a = *(const float4*)(qkv + base + 1024);
        b = *(const float4*)(qkv + base + 1028);
        *(float4*)&Vs[n * 36 + c0]     = a;
        *(float4*)&Vs[n * 36 + c0 + 4] = b;
    }
    if (tid < 225) bias_s[tid] = pos_emb[tid];
    __syncthreads();

    const int tq = tid >> 4;
    const int tk = tid & 15;

    float s[4][4];
#pragma unroll
    for (int a = 0; a < 4; a++)
#pragma unroll
        for (int b = 0; b < 4; b++) s[a][b] = 0.f;

#pragma unroll 8
    for (int d = 0; d < 32; d++) {
        float4 qf = *(const float4*)&Qt[d * 68 + tq * 4];
        float4 kf = *(const float4*)&Kt[d * 68 + tk * 4];
        const float* qa = (const float*)&qf;
        const float* ka = (const float*)&kf;
#pragma unroll
        for (int a = 0; a < 4; a++)
#pragma unroll
            for (int b = 0; b < 4; b++)
                s[a][b] = fmaf(qa[a], ka[b], s[a][b]);
    }

    const float scl = 0.17677669529663687f;
#pragma unroll
    for (int a = 0; a < 4; a++) {
        int q = tq * 4 + a, qh = q >> 3, qw = q & 7;
#pragma unroll
        for (int b = 0; b < 4; b++) {
            int k = tk * 4 + b, kh = k >> 3, kw = k & 7;
            s[a][b] = s[a][b] * scl + bias_s[(kh - qh + 7) * 15 + (kw - qw + 7)];
        }
    }

    float mx[4], sm[4];
#pragma unroll
    for (int a = 0; a < 4; a++)
        mx[a] = fmaxf(fmaxf(s[a][0], s[a][1]), fmaxf(s[a][2], s[a][3]));
#pragma unroll
    for (int off = 8; off; off >>= 1)
#pragma unroll
        for (int a = 0; a < 4; a++)
            mx[a] = fmaxf(mx[a], __shfl_xor_sync(0xffffffffu, mx[a], off));
#pragma unroll
    for (int a = 0; a < 4; a++) {
        sm[a] = 0.f;
#pragma unroll
        for (int b = 0; b < 4; b++) {
            s[a][b] = __expf(s[a][b] - mx[a]);
            sm[a] += s[a][b];
        }
    }
#pragma unroll
    for (int off = 8; off; off >>= 1)
#pragma unroll
        for (int a = 0; a < 4; a++)
            sm[a] += __shfl_xor_sync(0xffffffffu, sm[a], off);
    float inv[4];
#pragma unroll
    for (int a = 0; a < 4; a++) inv[a] = 1.f / sm[a];

#pragma unroll
    for (int b = 0; b < 4; b++) {
        float4 v = make_float4(s[0][b] * inv[0], s[1][b] * inv[1],
                               s[2][b] * inv[2], s[3][b] * inv[3]);
        *(float4*)&Pt[(tk * 4 + b) * 68 + tq * 4] = v;
    }
    __syncthreads();

    const int td = tid & 15;
    float o[4][2];
#pragma unroll
    for (int a = 0; a < 4; a++) { o[a][0] = 0.f; o[a][1] = 0.f; }
#pragma unroll 8
    for (int k = 0; k < 64; k++) {
        float4 pf = *(const float4*)&Pt[k * 68 + tq * 4];
        float2 vf = *(const float2*)&Vs[k * 36 + td * 2];
        const float* pa = (const float*)&pf;
#pragma unroll
        for (int a = 0; a < 4; a++) {
            o[a][0] = fmaf(pa[a], vf.x, o[a][0]);
            o[a][1] = fmaf(pa[a], vf.y, o[a][1]);
        }
    }
#pragma unroll
    for (int a = 0; a < 4; a++) {
        int q = tq * 4 + a;
        size_t ob = ((size_t)win * 64 + q) * (size_t)E_DIM + head * HD_ + td * 2;
        *(float2*)&out[ob] = make_float2(o[a][0], o[a][1]);
    }
}

// ---------------------------------------------------------------------------
// out[row] = LayerNorm(a[row] + b[row]) * g + be
// ---------------------------------------------------------------------------
__global__ void __launch_bounds__(128) add_ln_kernel(
    const float* __restrict__ A, const float* __restrict__ Bv,
    const float* __restrict__ g, const float* __restrict__ be,
    float* __restrict__ out)
{
    const int row = blockIdx.x;
    const int tid = threadIdx.x;
    size_t base = (size_t)row * E_DIM + tid * 4;

    float4 a = *(const float4*)(A + base);
    float4 b = *(const float4*)(Bv + base);
    float y0 = a.x + b.x, y1 = a.y + b.y, y2 = a.z + b.z, y3 = a.w + b.w;

    float s  = y0 + y1 + y2 + y3;
    float s2 = y0 * y0 + y1 * y1 + y2 * y2 + y3 * y3;
#pragma unroll
    for (int off = 16; off; off >>= 1) {
        s  += __shfl_down_sync(0xffffffffu, s, off);
        s2 += __shfl_down_sync(0xffffffffu, s2, off);
    }
    __shared__ float ss[4], ss2[4];
    int warp = tid >> 5, lane = tid & 31;
    if (lane == 0) { ss[warp] = s; ss2[warp] = s2; }
    __syncthreads();
    s  = ss[0] + ss[1] + ss[2] + ss[3];
    s2 = ss2[0] + ss2[1] + ss2[2] + ss2[3];

    const float rE = 1.f / 512.f;
    float mean = s * rE;
    float var  = s2 * rE - mean * mean;
    float rstd = rsqrtf(var + 1e-5f);

    int e = tid * 4;
    float4 gw = *(const float4*)(g + e);
    float4 bb = *(const float4*)(be + e);
    float4 o;
    o.x = (y0 - mean) * rstd * gw.x + bb.x;
    o.y = (y1 - mean) * rstd * gw.y + bb.y;
    o.z = (y2 - mean) * rstd * gw.z + bb.z;
    o.w = (y3 - mean) * rstd * gw.w + bb.w;
    *(float4*)(out + base) = o;
}

// ---------------------------------------------------------------------------
extern "C" void kernel_launch(void* const* d_in, const int* in_sizes, int n_in,
                              void* d_out, int out_size)
{
    const float* x     = (const float*)d_in[0];
    const float* w_qkv = (const float*)d_in[1];
    const float* b_qkv = (const float*)d_in[2];
    const float* w_out = (const float*)d_in[3];
    const float* b_out = (const float*)d_in[4];
    const float* pos   = (const float*)d_in[5];
    const float* w1    = (const float*)d_in[6];
    const float* b1    = (const float*)d_in[7];
    const float* w2    = (const float*)d_in[8];
    const float* b2    = (const float*)d_in[9];
    const float* ln1w  = (const float*)d_in[10];
    const float* ln1b  = (const float*)d_in[11];
    const float* ln2w  = (const float*)d_in[12];
    const float* ln2b  = (const float*)d_in[13];
    float* out = (float*)d_out;

    static float *p_qkv = nullptr, *p_attn = nullptr, *p_t0 = nullptr,
                 *p_z = nullptr, *p_h = nullptr;
    if (!p_qkv) {
        cudaGetSymbolAddress((void**)&p_qkv,  g_qkv);
        cudaGetSymbolAddress((void**)&p_attn, g_attn);
        cudaGetSymbolAddress((void**)&p_t0,   g_t0);
        cudaGetSymbolAddress((void**)&p_z,    g_z);
        cudaGetSymbolAddress((void**)&p_h,    g_h);
    }

    // 1. QKV projection -> window layout
    gemm_tf32<0, 1><<<dim3(QKV_N / 128, T_TOK / 128), 256>>>(
        x, w_qkv, b_qkv, p_qkv, T_TOK, QKV_N, E_DIM);

    // 2. window attention
    attn_kernel<<<dim3(NWIN, NH_), 256>>>(p_qkv, pos, p_attn);

    // 3. output projection -> token layout
    gemm_tf32<0, 2><<<dim3(E_DIM / 128, T_TOK / 128), 256>>>(
        p_attn, w_out, b_out, p_t0, T_TOK, E_DIM, E_DIM);

    // 4. residual + LN1
    add_ln_kernel<<<T_TOK, 128>>>(x, p_t0, ln1w, ln1b, p_z);

    // 5. FFN up + ReLU
    gemm_tf32<1, 0><<<dim3(DFF_N / 128, T_TOK / 128), 256>>>(
        p_z, w1, b1, p_h, T_TOK, DFF_N, E_DIM);

    // 6. FFN down
    gemm_tf32<0, 0><<<dim3(E_DIM / 128, T_TOK / 128), 256>>>(
        p_h, w2, b2, p_t0, T_TOK, E_DIM, DFF_N);

    // 7. residual + LN2 -> output
    add_ln_kernel<<<T_TOK, 128>>>(p_z, p_t0, ln2w, ln2b, out);
}

// round 6
// speedup vs baseline: 3.9472x; 1.2261x over previous
#include <cuda_runtime.h>
#include <cuda_bf16.h>
#include <cstdint>
#include <math.h>

// ---------------------------------------------------------------------------
// Swin Transformer encoder layer, GB300 round-6:
// tf32 mma.sync GEMM + cp.async 4-stage pipeline (no register staging).
// ---------------------------------------------------------------------------

#define T_TOK   65536
#define E_DIM   512
#define QKV_N   1536
#define DFF_N   2048
#define NWIN    1024
#define NH_     16
#define HD_     32

__device__ float g_qkv[(size_t)T_TOK * QKV_N];
__device__ float g_attn[(size_t)T_TOK * E_DIM];
__device__ float g_t0[(size_t)T_TOK * E_DIM];
__device__ float g_z[(size_t)T_TOK * E_DIM];
__device__ float g_h[(size_t)T_TOK * DFF_N];

__device__ __forceinline__ int to_win_row(int m) {
    int b = m >> 14, p = m & 16383;
    int r = p >> 7, c = p & 127;
    int win = (b << 8) + ((r >> 3) << 4) + (c >> 3);
    int n   = ((r & 7) << 3) + (c & 7);
    return (win << 6) + n;
}
__device__ __forceinline__ int from_win_row(int m) {
    int win = m >> 6, n = m & 63;
    int b  = win >> 8, wi = win & 255;
    int wr = wi >> 4,  wc = wi & 15;
    int r = (wr << 3) + (n >> 3);
    int c = (wc << 3) + (n & 7);
    return (b << 14) + (r << 7) + c;
}

__device__ __forceinline__ void mma_tf32(float c[4], const uint32_t a[4], const uint32_t b[2]) {
    asm volatile(
        "mma.sync.aligned.m16n8k8.row.col.f32.tf32.tf32.f32 "
        "{%0,%1,%2,%3},{%4,%5,%6,%7},{%8,%9},{%0,%1,%2,%3};\n"
        : "+f"(c[0]), "+f"(c[1]), "+f"(c[2]), "+f"(c[3])
        : "r"(a[0]), "r"(a[1]), "r"(a[2]), "r"(a[3]), "r"(b[0]), "r"(b[1]));
}

__device__ __forceinline__ void ldsm4(uint32_t& r0, uint32_t& r1, uint32_t& r2, uint32_t& r3,
                                      uint32_t addr) {
    asm volatile("ldmatrix.sync.aligned.m8n8.x4.shared.b16 {%0,%1,%2,%3}, [%4];"
                 : "=r"(r0), "=r"(r1), "=r"(r2), "=r"(r3) : "r"(addr));
}

__device__ __forceinline__ void cpasync16(uint32_t dst, const float* src) {
    asm volatile("cp.async.cg.shared.global [%0], [%1], 16;" :: "r"(dst), "l"(src));
}
__device__ __forceinline__ void cp_commit() {
    asm volatile("cp.async.commit_group;" ::: "memory");
}
template <int N>
__device__ __forceinline__ void cp_wait() {
    asm volatile("cp.async.wait_group %0;" :: "n"(N) : "memory");
}

// ---------------------------------------------------------------------------
// TF32 NT GEMM: C[m][n] = sum_k A[m][k]*B[n][k] + bias[n].
// Block 128x128, BK=16, 256 threads (8 warps as 2x4), warp tile 64x32.
// Smem: k-major 128x16 tiles, XOR swizzle (chunk ^= (row>>1)&3); 4-stage
// cp.async ring; ldmatrix.x4.b16 fragment reads; raw fp32 bits fed to
// tf32 mma (HW truncation).
// EPI: 0 bias, 1 bias+relu.  PERM: 0 none, 1 to_win, 2 from_win.
// ---------------------------------------------------------------------------
#define STAGES 4
#define GSM_BYTES (STAGES * 8192 * 2)

template <int EPI, int PERM>
__global__ void __launch_bounds__(256, 2) gemm_tf32(
    const float* __restrict__ A, const float* __restrict__ B,
    const float* __restrict__ bias, float* __restrict__ C,
    int M, int N, int K)
{
    extern __shared__ __align__(128) uint32_t smem[];
    const uint32_t asb = (uint32_t)__cvta_generic_to_shared(smem);            // A stages
    const uint32_t bsb = asb + STAGES * 8192;                                  // B stages

    const int tid  = threadIdx.x;
    const int lane = tid & 31;
    const int warp = tid >> 5;
    const int wr = warp >> 2;        // m half (64 rows)
    const int wc = warp & 3;         // n quarter (32 cols)
    const int bm = blockIdx.y << 7;
    const int bn = blockIdx.x << 7;

    // loader: thread -> row = tid>>2 (+64), k chunk = tid&3 (4 floats)
    const int lrow = tid >> 2;
    const int lk   = (tid & 3) << 2;
    const int sw   = (((lk >> 2) ^ ((lrow >> 1) & 3)) << 2);
    const uint32_t aoff0 = (uint32_t)(lrow * 16 + sw) * 4u;        // byte offset
    const uint32_t aoff1 = aoff0 + 64 * 16 * 4;

    const float* aP0 = A + (size_t)(bm + lrow) * K + lk;
    const float* aP1 = A + (size_t)(bm + lrow + 64) * K + lk;
    const float* bP0 = B + (size_t)(bn + lrow) * K + lk;
    const float* bP1 = B + (size_t)(bn + lrow + 64) * K + lk;

    // ldmatrix lane invariants
    const int lm   = (lane & 7) + (((lane >> 3) & 1) << 3);
    const int ahik = lane >> 4;
    const int amsw = (lm >> 1) & 3;
    const int brow = lane & 7;
    const int bnt2 = (lane >> 4) & 1;
    const int bhik = (lane >> 3) & 1;
    const int bmsw = (brow >> 1) & 3;

    float acc[4][4][4];
#pragma unroll
    for (int i = 0; i < 4; i++)
#pragma unroll
        for (int j = 0; j < 4; j++)
#pragma unroll
            for (int v = 0; v < 4; v++) acc[i][j][v] = 0.f;

    const int ntiles = K >> 4;

    // prologue: stages 0..2
#pragma unroll
    for (int s = 0; s < STAGES - 1; s++) {
        const int kk = s << 4;
        const uint32_t sa = asb + s * 8192;
        const uint32_t sb = bsb + s * 8192;
        cpasync16(sa + aoff0, aP0 + kk);
        cpasync16(sa + aoff1, aP1 + kk);
        cpasync16(sb + aoff0, bP0 + kk);
        cpasync16(sb + aoff1, bP1 + kk);
        cp_commit();
    }

    for (int t = 0; t < ntiles; t++) {
        cp_wait<STAGES - 2>();
        __syncthreads();

        // issue tile t+3 into slot (t+3)%4 (overwrites consumed tile t-1)
        if (t + STAGES - 1 < ntiles) {
            const int s = (t + STAGES - 1) & (STAGES - 1);
            const int kk = (t + STAGES - 1) << 4;
            const uint32_t sa = asb + s * 8192;
            const uint32_t sb = bsb + s * 8192;
            cpasync16(sa + aoff0, aP0 + kk);
            cpasync16(sa + aoff1, aP1 + kk);
            cpasync16(sb + aoff0, bP0 + kk);
            cpasync16(sb + aoff1, bP1 + kk);
            cp_commit();
        }

        const int cur = t & (STAGES - 1);
        const uint32_t abuf = asb + cur * 8192;
        const uint32_t bbuf = bsb + cur * 8192;
#pragma unroll
        for (int s = 0; s < 2; s++) {
            uint32_t afr[4][4];
#pragma unroll
            for (int i = 0; i < 4; i++) {
                int m = wr * 64 + i * 16 + lm;
                int chunk = (s * 2 + ahik) ^ amsw;
                ldsm4(afr[i][0], afr[i][1], afr[i][2], afr[i][3],
                      abuf + (uint32_t)(m * 16 + chunk * 4) * 4u);
            }
            uint32_t bfr[4][2];
#pragma unroll
            for (int jj = 0; jj < 2; jj++) {
                int ntile = wc * 4 + 2 * jj + bnt2;
                int n = ntile * 8 + brow;
                int chunk = (s * 2 + bhik) ^ bmsw;
                ldsm4(bfr[2 * jj][0], bfr[2 * jj][1], bfr[2 * jj + 1][0], bfr[2 * jj + 1][1],
                      bbuf + (uint32_t)(n * 16 + chunk * 4) * 4u);
            }
#pragma unroll
            for (int i = 0; i < 4; i++)
#pragma unroll
                for (int j = 0; j < 4; j++)
                    mma_tf32(acc[i][j], afr[i], bfr[j]);
        }
    }

    // epilogue
    const int r  = lane >> 2;
    const int cc = (lane & 3) << 1;
#pragma unroll
    for (int i = 0; i < 4; i++) {
        int row0 = bm + wr * 64 + i * 16 + r;
        int row1 = row0 + 8;
        int o0, o1;
        if (PERM == 0)      { o0 = row0;               o1 = row1; }
        else if (PERM == 1) { o0 = to_win_row(row0);   o1 = to_win_row(row1); }
        else                { o0 = from_win_row(row0); o1 = from_win_row(row1); }
#pragma unroll
        for (int j = 0; j < 4; j++) {
            int gn = bn + wc * 32 + j * 8 + cc;
            float b0 = bias[gn], b1 = bias[gn + 1];
            float v00 = acc[i][j][0] + b0, v01 = acc[i][j][1] + b1;
            float v10 = acc[i][j][2] + b0, v11 = acc[i][j][3] + b1;
            if (EPI == 1) {
                v00 = fmaxf(v00, 0.f); v01 = fmaxf(v01, 0.f);
                v10 = fmaxf(v10, 0.f); v11 = fmaxf(v11, 0.f);
            }
            *(float2*)&C[(size_t)o0 * N + gn] = make_float2(v00, v01);
            *(float2*)&C[(size_t)o1 * N + gn] = make_float2(v10, v11);
        }
    }
}

// ---------------------------------------------------------------------------
// Window attention: one block per (window, head). 4x4 register micro-tiles.
// ---------------------------------------------------------------------------
__global__ void __launch_bounds__(256) attn_kernel(
    const float* __restrict__ qkv, const float* __restrict__ pos_emb,
    float* __restrict__ out)
{
    const int win = blockIdx.x;
    const int head = blockIdx.y;
    const int tid = threadIdx.x;

    __shared__ float Qt[32 * 68];
    __shared__ float Kt[32 * 68];
    __shared__ float Vs[64 * 36];
    __shared__ float Pt[64 * 68];
    __shared__ float bias_s[225];

    {
        int n  = tid >> 2;
        int c0 = (tid & 3) << 3;
        size_t base = ((size_t)win * 64 + n) * (size_t)QKV_N + head * HD_ + c0;
        float4 a = *(const float4*)(qkv + base);
        float4 b = *(const float4*)(qkv + base + 4);
        Qt[(c0 + 0) * 68 + n] = a.x; Qt[(c0 + 1) * 68 + n] = a.y;
        Qt[(c0 + 2) * 68 + n] = a.z; Qt[(c0 + 3) * 68 + n] = a.w;
        Qt[(c0 + 4) * 68 + n] = b.x; Qt[(c0 + 5) * 68 + n] = b.y;
        Qt[(c0 + 6) * 68 + n] = b.z; Qt[(c0 + 7) * 68 + n] = b.w;
        a = *(const float4*)(qkv + base + 512);
        b = *(const float4*)(qkv + base + 516);
        Kt[(c0 + 0) * 68 + n] = a.x; Kt[(c0 + 1) * 68 + n] = a.y;
        Kt[(c0 + 2) * 68 + n] = a.z; Kt[(c0 + 3) * 68 + n] = a.w;
        Kt[(c0 + 4) * 68 + n] = b.x; Kt[(c0 + 5) * 68 + n] = b.y;
        Kt[(c0 + 6) * 68 + n] = b.z; Kt[(c0 + 7) * 68 + n] = b.w;
        a = *(const float4*)(qkv + base + 1024);
        b = *(const float4*)(qkv + base + 1028);
        *(float4*)&Vs[n * 36 + c0]     = a;
        *(float4*)&Vs[n * 36 + c0 + 4] = b;
    }
    if (tid < 225) bias_s[tid] = pos_emb[tid];
    __syncthreads();

    const int tq = tid >> 4;
    const int tk = tid & 15;

    float s[4][4];
#pragma unroll
    for (int a = 0; a < 4; a++)
#pragma unroll
        for (int b = 0; b < 4; b++) s[a][b] = 0.f;

#pragma unroll 8
    for (int d = 0; d < 32; d++) {
        float4 qf = *(const float4*)&Qt[d * 68 + tq * 4];
        float4 kf = *(const float4*)&Kt[d * 68 + tk * 4];
        const float* qa = (const float*)&qf;
        const float* ka = (const float*)&kf;
#pragma unroll
        for (int a = 0; a < 4; a++)
#pragma unroll
            for (int b = 0; b < 4; b++)
                s[a][b] = fmaf(qa[a], ka[b], s[a][b]);
    }

    const float scl = 0.17677669529663687f;
#pragma unroll
    for (int a = 0; a < 4; a++) {
        int q = tq * 4 + a, qh = q >> 3, qw = q & 7;
#pragma unroll
        for (int b = 0; b < 4; b++) {
            int k = tk * 4 + b, kh = k >> 3, kw = k & 7;
            s[a][b] = s[a][b] * scl + bias_s[(kh - qh + 7) * 15 + (kw - qw + 7)];
        }
    }

    float mx[4], sm[4];
#pragma unroll
    for (int a = 0; a < 4; a++)
        mx[a] = fmaxf(fmaxf(s[a][0], s[a][1]), fmaxf(s[a][2], s[a][3]));
#pragma unroll
    for (int off = 8; off; off >>= 1)
#pragma unroll
        for (int a = 0; a < 4; a++)
            mx[a] = fmaxf(mx[a], __shfl_xor_sync(0xffffffffu, mx[a], off));
#pragma unroll
    for (int a = 0; a < 4; a++) {
        sm[a] = 0.f;
#pragma unroll
        for (int b = 0; b < 4; b++) {
            s[a][b] = __expf(s[a][b] - mx[a]);
            sm[a] += s[a][b];
        }
    }
#pragma unroll
    for (int off = 8; off; off >>= 1)
#pragma unroll
        for (int a = 0; a < 4; a++)
            sm[a] += __shfl_xor_sync(0xffffffffu, sm[a], off);
    float inv[4];
#pragma unroll
    for (int a = 0; a < 4; a++) inv[a] = 1.f / sm[a];

#pragma unroll
    for (int b = 0; b < 4; b++) {
        float4 v = make_float4(s[0][b] * inv[0], s[1][b] * inv[1],
                               s[2][b] * inv[2], s[3][b] * inv[3]);
        *(float4*)&Pt[(tk * 4 + b) * 68 + tq * 4] = v;
    }
    __syncthreads();

    const int td = tid & 15;
    float o[4][2];
#pragma unroll
    for (int a = 0; a < 4; a++) { o[a][0] = 0.f; o[a][1] = 0.f; }
#pragma unroll 8
    for (int k = 0; k < 64; k++) {
        float4 pf = *(const float4*)&Pt[k * 68 + tq * 4];
        float2 vf = *(const float2*)&Vs[k * 36 + td * 2];
        const float* pa = (const float*)&pf;
#pragma unroll
        for (int a = 0; a < 4; a++) {
            o[a][0] = fmaf(pa[a], vf.x, o[a][0]);
            o[a][1] = fmaf(pa[a], vf.y, o[a][1]);
        }
    }
#pragma unroll
    for (int a = 0; a < 4; a++) {
        int q = tq * 4 + a;
        size_t ob = ((size_t)win * 64 + q) * (size_t)E_DIM + head * HD_ + td * 2;
        *(float2*)&out[ob] = make_float2(o[a][0], o[a][1]);
    }
}

// ---------------------------------------------------------------------------
// out[row] = LayerNorm(a[row] + b[row]) * g + be
// ---------------------------------------------------------------------------
__global__ void __launch_bounds__(128) add_ln_kernel(
    const float* __restrict__ A, const float* __restrict__ Bv,
    const float* __restrict__ g, const float* __restrict__ be,
    float* __restrict__ out)
{
    const int row = blockIdx.x;
    const int tid = threadIdx.x;
    size_t base = (size_t)row * E_DIM + tid * 4;

    float4 a = *(const float4*)(A + base);
    float4 b = *(const float4*)(Bv + base);
    float y0 = a.x + b.x, y1 = a.y + b.y, y2 = a.z + b.z, y3 = a.w + b.w;

    float s  = y0 + y1 + y2 + y3;
    float s2 = y0 * y0 + y1 * y1 + y2 * y2 + y3 * y3;
#pragma unroll
    for (int off = 16; off; off >>= 1) {
        s  += __shfl_down_sync(0xffffffffu, s, off);
        s2 += __shfl_down_sync(0xffffffffu, s2, off);
    }
    __shared__ float ss[4], ss2[4];
    int warp = tid >> 5, lane = tid & 31;
    if (lane == 0) { ss[warp] = s; ss2[warp] = s2; }
    __syncthreads();
    s  = ss[0] + ss[1] + ss[2] + ss[3];
    s2 = ss2[0] + ss2[1] + ss2[2] + ss2[3];

    const float rE = 1.f / 512.f;
    float mean = s * rE;
    float var  = s2 * rE - mean * mean;
    float rstd = rsqrtf(var + 1e-5f);

    int e = tid * 4;
    float4 gw = *(const float4*)(g + e);
    float4 bb = *(const float4*)(be + e);
    float4 o;
    o.x = (y0 - mean) * rstd * gw.x + bb.x;
    o.y = (y1 - mean) * rstd * gw.y + bb.y;
    o.z = (y2 - mean) * rstd * gw.z + bb.z;
    o.w = (y3 - mean) * rstd * gw.w + bb.w;
    *(float4*)(out + base) = o;
}

// ---------------------------------------------------------------------------
extern "C" void kernel_launch(void* const* d_in, const int* in_sizes, int n_in,
                              void* d_out, int out_size)
{
    const float* x     = (const float*)d_in[0];
    const float* w_qkv = (const float*)d_in[1];
    const float* b_qkv = (const float*)d_in[2];
    const float* w_out = (const float*)d_in[3];
    const float* b_out = (const float*)d_in[4];
    const float* pos   = (const float*)d_in[5];
    const float* w1    = (const float*)d_in[6];
    const float* b1    = (const float*)d_in[7];
    const float* w2    = (const float*)d_in[8];
    const float* b2    = (const float*)d_in[9];
    const float* ln1w  = (const float*)d_in[10];
    const float* ln1b  = (const float*)d_in[11];
    const float* ln2w  = (const float*)d_in[12];
    const float* ln2b  = (const float*)d_in[13];
    float* out = (float*)d_out;

    static float *p_qkv = nullptr, *p_attn = nullptr, *p_t0 = nullptr,
                 *p_z = nullptr, *p_h = nullptr;
    static bool inited = false;
    if (!inited) {
        cudaGetSymbolAddress((void**)&p_qkv,  g_qkv);
        cudaGetSymbolAddress((void**)&p_attn, g_attn);
        cudaGetSymbolAddress((void**)&p_t0,   g_t0);
        cudaGetSymbolAddress((void**)&p_z,    g_z);
        cudaGetSymbolAddress((void**)&p_h,    g_h);
        cudaFuncSetAttribute(gemm_tf32<0, 1>, cudaFuncAttributeMaxDynamicSharedMemorySize, GSM_BYTES);
        cudaFuncSetAttribute(gemm_tf32<0, 2>, cudaFuncAttributeMaxDynamicSharedMemorySize, GSM_BYTES);
        cudaFuncSetAttribute(gemm_tf32<1, 0>, cudaFuncAttributeMaxDynamicSharedMemorySize, GSM_BYTES);
        cudaFuncSetAttribute(gemm_tf32<0, 0>, cudaFuncAttributeMaxDynamicSharedMemorySize, GSM_BYTES);
        inited = true;
    }

    // 1. QKV projection -> window layout
    gemm_tf32<0, 1><<<dim3(QKV_N / 128, T_TOK / 128), 256, GSM_BYTES>>>(
        x, w_qkv, b_qkv, p_qkv, T_TOK, QKV_N, E_DIM);

    // 2. window attention
    attn_kernel<<<dim3(NWIN, NH_), 256>>>(p_qkv, pos, p_attn);

    // 3. output projection -> token layout
    gemm_tf32<0, 2><<<dim3(E_DIM / 128, T_TOK / 128), 256, GSM_BYTES>>>(
        p_attn, w_out, b_out, p_t0, T_TOK, E_DIM, E_DIM);

    // 4. residual + LN1
    add_ln_kernel<<<T_TOK, 128>>>(x, p_t0, ln1w, ln1b, p_z);

    // 5. FFN up + ReLU
    gemm_tf32<1, 0><<<dim3(DFF_N / 128, T_TOK / 128), 256, GSM_BYTES>>>(
        p_z, w1, b1, p_h, T_TOK, DFF_N, E_DIM);

    // 6. FFN down
    gemm_tf32<0, 0><<<dim3(E_DIM / 128, T_TOK / 128), 256, GSM_BYTES>>>(
        p_h, w2, b2, p_t0, T_TOK, E_DIM, DFF_N);

    // 7. residual + LN2 -> output
    add_ln_kernel<<<T_TOK, 128>>>(p_z, p_t0, ln2w, ln2b, out);
}